// round 4
// baseline (speedup 1.0000x reference)
#include <cuda_runtime.h>

#define NC   14
#define H    2048
#define W    2048
#define HW   (H * W)
#define TILE 32
#define HD   34          // tile + halo rows
#define STR  36          // smem row stride (floats); cols 0..32 data, col 34 = left halo
#define GB   64          // blocks per grid dim
#define NBLK (GB * GB)

// Per-block, per-channel partials (fixed slots -> deterministic)
__device__ __align__(16) float g_min[NC * NBLK];
__device__ __align__(16) float g_sum[NC * NBLK];
__device__ __align__(16) float g_cnt[NC * NBLK];
__device__ __align__(16) float g_t1 [NC * NBLK];
__device__ __align__(16) float g_t2 [NC * NBLK];
__device__ float g_loss[NC];
__device__ unsigned int g_ctr;   // zero-init; reset by last reduce block each run

extern __shared__ float sp[];    // [NC][HD][STR] probs

__device__ __forceinline__ float* SP(int ch, int r) {
    return sp + (ch * HD + r) * STR;
}

// window cols: v[0]=col lcol (left nb), v[1..4]=cols cb..cb+3 (centers), v[5]=col cb+4
__device__ __forceinline__ void loadrow(float v[6], const float* row, int cb, int lcol) {
    v[0] = row[lcol];
    float4 q = *(const float4*)(row + cb);
    v[1] = q.x; v[2] = q.y; v[3] = q.z; v[4] = q.w;
    v[5] = row[cb + 4];
}

__device__ __forceinline__ void hmax3(float m[4], const float v[6]) {
    #pragma unroll
    for (int i = 0; i < 4; i++)
        m[i] = fmaxf(fmaxf(v[i], v[i + 1]), v[i + 2]);
}

__global__ __launch_bounds__(512, 3)
void tile_kernel(const float* __restrict__ in) {
    const int tid = threadIdx.x;
    const int bx = blockIdx.x, by = blockIdx.y;

    // ---- Phase 1: softmax probs into smem.
    // Vector tasks (tid<272): row r (0..33), col group k (0..7) -> cols 4k..4k+3, aligned.
    // Scalar tasks (272..339): right edge col 32 and left halo col -1 (stored at col 34).
    // Logits ~N(0,1): exp can't overflow, skip max-subtraction.
    if (tid < 272) {
        const int r = tid >> 3, k = tid & 7;
        const int gy = by * TILE - 1 + r;
        const int col = 4 * k;
        if ((unsigned)gy < H) {
            const float* g = in + gy * W + bx * TILE + col;
            float4 d4 = make_float4(0.f, 0.f, 0.f, 0.f);
            #pragma unroll
            for (int ch = 0; ch < NC; ch++) {
                float4 x = *(const float4*)(g + ch * HW);
                float4 e;
                e.x = __expf(x.x); e.y = __expf(x.y);
                e.z = __expf(x.z); e.w = __expf(x.w);
                d4.x += e.x; d4.y += e.y; d4.z += e.z; d4.w += e.w;
                *(float4*)(SP(ch, r) + col) = e;          // unnormalized exp
            }
            float4 rd;
            rd.x = __fdividef(1.f, d4.x); rd.y = __fdividef(1.f, d4.y);
            rd.z = __fdividef(1.f, d4.z); rd.w = __fdividef(1.f, d4.w);
            #pragma unroll
            for (int ch = 0; ch < NC; ch++) {
                float* srow = SP(ch, r) + col;
                float4 e = *(float4*)srow;
                e.x *= rd.x; e.y *= rd.y; e.z *= rd.z; e.w *= rd.w;
                *(float4*)srow = e;
            }
        } else {
            const float4 m = make_float4(-1.f, -1.f, -1.f, -1.f);
            #pragma unroll
            for (int ch = 0; ch < NC; ch++)
                *(float4*)(SP(ch, r) + col) = m;          // -inf padding proxy
        }
    } else if (tid < 340) {
        const int t   = tid - 272;
        const int isL = (t >= 34);                 // left-halo task vs right-edge task
        const int r   = isL ? (t - 34) : t;
        const int gy  = by * TILE - 1 + r;
        const int gx  = isL ? (bx * TILE - 1) : (bx * TILE + 32);
        const int col = isL ? 34 : 32;
        if ((unsigned)gy < H && (unsigned)gx < W) {
            const float* g = in + gy * W + gx;
            float d = 0.f;
            #pragma unroll
            for (int ch = 0; ch < NC; ch++) {
                float e = __expf(g[ch * HW]);
                d += e;
                SP(ch, r)[col] = e;
            }
            float rd = __fdividef(1.f, d);
            #pragma unroll
            for (int ch = 0; ch < NC; ch++)
                SP(ch, r)[col] *= rd;
        } else {
            #pragma unroll
            for (int ch = 0; ch < NC; ch++)
                SP(ch, r)[col] = -1.f;
        }
    }
    __syncthreads();

    // ---- Phase 2: warp w owns channel w; lane streams 8 rows x 4 cols.
    const int wid  = tid >> 5;
    const int lane = tid & 31;
    if (wid < NC) {
        const int ch   = wid;
        const int sx   = lane & 7;
        const int cb   = 4 * sx;              // center cols cb..cb+3 (0..31)
        const int lcol = (sx == 0) ? 34 : (cb - 1);
        const int r0   = 8 * (lane >> 3);     // rows r0..r0+9, centers r0+1..r0+8
        const float* base = SP(ch, r0);

        float amin = 1e30f, asum = 0.f, acnt = 0.f, t1 = -1e30f, t2 = -1e30f;

        float v[2][6];
        float m3[3][4];
        {
            float vt[6];
            loadrow(vt, base, cb, lcol);               // row r0 (above)
            hmax3(m3[0], vt);
        }
        loadrow(v[1], base + STR, cb, lcol);           // row r0+1 = first center
        hmax3(m3[1], v[1]);

        #pragma unroll
        for (int j = 0; j < 8; j++) {
            float* vC = v[1 - (j & 1)];
            float* vB = v[j & 1];
            float* mA = m3[j % 3];
            float* mB = m3[(j + 2) % 3];
            loadrow(vB, base + (j + 2) * STR, cb, lcol);   // row below center
            hmax3(mB, vB);
            #pragma unroll
            for (int i = 0; i < 4; i++) {
                float p  = vC[i + 1];
                float nb = fmaxf(fmaxf(mA[i], mB[i]), fmaxf(vC[i], vC[i + 2]));
                amin = fminf(amin, p);
                bool  m  = p > nb;                     // strict 8-neighbor local max
                float pv = m ? p : -1e30f;
                asum += m ? p : 0.f;
                acnt += m ? 1.f : 0.f;
                t2 = fmaxf(t2, fminf(t1, pv));
                t1 = fmaxf(t1, pv);
            }
        }

        // warp reduction (whole channel lives in this warp)
        #pragma unroll
        for (int off = 16; off > 0; off >>= 1) {
            amin = fminf(amin, __shfl_down_sync(0xffffffffu, amin, off));
            asum += __shfl_down_sync(0xffffffffu, asum, off);
            acnt += __shfl_down_sync(0xffffffffu, acnt, off);
            float b1 = __shfl_down_sync(0xffffffffu, t1, off);
            float b2 = __shfl_down_sync(0xffffffffu, t2, off);
            float lo = fminf(t1, b1);
            t1 = fmaxf(t1, b1);
            t2 = fmaxf(lo, fmaxf(t2, b2));
        }
        if (lane == 0) {
            int bid = by * GB + bx;
            int idx = ch * NBLK + bid;
            g_min[idx] = amin; g_sum[idx] = asum; g_cnt[idx] = acnt;
            g_t1[idx]  = t1;   g_t2[idx]  = t2;
        }
    }
}

// 14 blocks x 1024 threads: block c reduces channel c (one float4 per array per thread);
// last block folds the 14 channel losses into the scalar output.
__global__ void reduce_kernel(float* __restrict__ out) {
    __shared__ float s[32][5];
    const int c    = blockIdx.x;
    const int tid  = threadIdx.x;
    const int lane = tid & 31;
    const int warp = tid >> 5;
    const int base = c * NBLK + 4 * tid;

    float4 m4 = *(const float4*)(g_min + base);
    float4 s4 = *(const float4*)(g_sum + base);
    float4 c4 = *(const float4*)(g_cnt + base);
    float4 a4 = *(const float4*)(g_t1  + base);
    float4 b4 = *(const float4*)(g_t2  + base);

    float mn = fminf(fminf(m4.x, m4.y), fminf(m4.z, m4.w));
    float sm = (s4.x + s4.y) + (s4.z + s4.w);
    float ct = (c4.x + c4.y) + (c4.z + c4.w);
    // top-2 merge across the 4 (t1,t2) pairs
    float t1 = a4.x, t2 = b4.x;
    {
        float lo = fminf(t1, a4.y); t1 = fmaxf(t1, a4.y); t2 = fmaxf(lo, fmaxf(t2, b4.y));
        lo = fminf(t1, a4.z); t1 = fmaxf(t1, a4.z); t2 = fmaxf(lo, fmaxf(t2, b4.z));
        lo = fminf(t1, a4.w); t1 = fmaxf(t1, a4.w); t2 = fmaxf(lo, fmaxf(t2, b4.w));
    }

    #pragma unroll
    for (int off = 16; off > 0; off >>= 1) {
        mn = fminf(mn, __shfl_down_sync(0xffffffffu, mn, off));
        sm += __shfl_down_sync(0xffffffffu, sm, off);
        ct += __shfl_down_sync(0xffffffffu, ct, off);
        float b1 = __shfl_down_sync(0xffffffffu, t1, off);
        float b2 = __shfl_down_sync(0xffffffffu, t2, off);
        float lo = fminf(t1, b1);
        t1 = fmaxf(t1, b1);
        t2 = fmaxf(lo, fmaxf(t2, b2));
    }
    if (lane == 0) { s[warp][0]=mn; s[warp][1]=sm; s[warp][2]=ct; s[warp][3]=t1; s[warp][4]=t2; }
    __syncthreads();

    if (tid == 0) {
        mn = s[0][0]; sm = s[0][1]; ct = s[0][2]; t1 = s[0][3]; t2 = s[0][4];
        #pragma unroll
        for (int w = 1; w < 32; w++) {
            mn = fminf(mn, s[w][0]); sm += s[w][1]; ct += s[w][2];
            float b1 = s[w][3], b2 = s[w][4];
            float lo = fminf(t1, b1);
            t1 = fmaxf(t1, b1);
            t2 = fmaxf(lo, fmaxf(t2, b2));
        }
        float total = sm - ct * mn;           // sum of importances over maxima
        float v1 = t1 - mn, v2 = t2 - mn;
        int k = (c < 7) ? 1 : 2;
        float target = 0.f, hinge = 0.f;
        if (ct >= 1.f)           { target += v1; hinge += fmaxf(0.f, 1.f - v1); }
        if (k == 2 && ct >= 2.f) { target += v2; hinge += fmaxf(0.f, 1.f - v2); }
        g_loss[c] = (total - target) + hinge;

        __threadfence();
        unsigned int old = atomicAdd(&g_ctr, 1u);
        if (old == NC - 1) {                  // last block finalizes
            float ssum = 0.f;
            #pragma unroll
            for (int i = 0; i < NC; i++) ssum += g_loss[i];
            out[0] = ssum / (float)NC;
            g_ctr = 0;                        // reset for next graph replay
        }
    }
}

extern "C" void kernel_launch(void* const* d_in, const int* in_sizes, int n_in,
                              void* d_out, int out_size) {
    const float* in = (const float*)d_in[0];   // [1,14,2048,2048] f32 logits
    float* out = (float*)d_out;                // scalar f32

    const size_t smem = (size_t)NC * HD * STR * sizeof(float);   // 68544 B
    cudaFuncSetAttribute(tile_kernel, cudaFuncAttributeMaxDynamicSharedMemorySize, (int)smem);

    dim3 grid(GB, GB);
    tile_kernel<<<grid, 512, smem>>>(in);
    reduce_kernel<<<NC, 1024>>>(out);
}

// round 5
// speedup vs baseline: 1.5228x; 1.5228x over previous
#include <cuda_runtime.h>

#define NC   14
#define H    2048
#define W    2048
#define HW   (H * W)
#define TILE 32
#define HD   34          // tile + halo
#define STR  36          // padded smem row stride (floats)
#define GB   64          // blocks per grid dim
#define NBLK (GB * GB)

// Per-block, per-channel partials (fixed slots -> deterministic)
__device__ __align__(16) float g_min[NC * NBLK];
__device__ __align__(16) float g_sum[NC * NBLK];
__device__ __align__(16) float g_cnt[NC * NBLK];
__device__ __align__(16) float g_t1 [NC * NBLK];
__device__ __align__(16) float g_t2 [NC * NBLK];
__device__ float g_loss[NC];
__device__ unsigned int g_ctr;   // zero-init; reset by last reduce block each run

extern __shared__ float sp[];    // [NC][HD][STR] probs

__device__ __forceinline__ float* SP(int ch, int r) {
    return sp + (ch * HD + r) * STR;
}

__device__ __forceinline__ void loadrow6(float v[6], const float* row) {
    float4 a = *(const float4*)row;          // cols 0..3
    float2 b = *(const float2*)(row + 4);    // cols 4..5
    v[0] = a.x; v[1] = a.y; v[2] = a.z; v[3] = a.w;
    v[4] = b.x; v[5] = b.y;
}

__device__ __forceinline__ void hmax3(float m[4], const float v[6]) {
    #pragma unroll
    for (int i = 0; i < 4; i++)
        m[i] = fmaxf(fmaxf(v[i], v[i + 1]), v[i + 2]);
}

__global__ __launch_bounds__(512, 2)   // 64-reg budget: no spills; 2 blocks/SM (50% occ)
void tile_kernel(const float* __restrict__ in) {
    const int tid = threadIdx.x;
    const int x0 = blockIdx.x * TILE - 1;
    const int y0 = blockIdx.y * TILE - 1;

    // ---- Phase 1: load logits (tile+halo), softmax over 14 channels -> smem probs.
    // Logits ~N(0,1): exp can't overflow, skip max-subtraction.
    for (int i = tid; i < HD * HD; i += 512) {
        int r = i / HD;
        int c = i - r * HD;
        int gy = y0 + r, gx = x0 + c;
        if ((unsigned)gy < H && (unsigned)gx < W) {
            const float* g = in + gy * W + gx;
            float e[NC];
            float d = 0.f;
            #pragma unroll
            for (int ch = 0; ch < NC; ch++) {
                e[ch] = __expf(g[ch * HW]);
                d += e[ch];
            }
            float rd = __fdividef(1.0f, d);
            #pragma unroll
            for (int ch = 0; ch < NC; ch++)
                SP(ch, r)[c] = e[ch] * rd;
        } else {
            #pragma unroll
            for (int ch = 0; ch < NC; ch++)
                SP(ch, r)[c] = -1.0f;   // -inf padding proxy (probs > 0 > -1)
        }
    }
    __syncthreads();

    // ---- Phase 2: warp w owns channel w; lane streams 8 rows x 4 cols.
    const int wid  = tid >> 5;
    const int lane = tid & 31;
    if (wid < NC) {
        const int ch = wid;
        const int cb = 4 * (lane & 7);     // window cols cb..cb+5, centers cb+1..cb+4
        const int r0 = 8 * (lane >> 3);    // window rows r0..r0+9, centers r0+1..r0+8
        const float* base = sp + (ch * HD + r0) * STR + cb;

        float amin = 1e30f, asum = 0.f, acnt = 0.f, t1 = -1e30f, t2 = -1e30f;

        float v[2][6];
        float m3[3][4];
        {
            float vt[6];
            loadrow6(vt, base);            // row r0 (above): only m3 needed
            hmax3(m3[0], vt);
        }
        loadrow6(v[1], base + STR);        // row r0+1 = first center
        hmax3(m3[1], v[1]);

        #pragma unroll
        for (int j = 0; j < 8; j++) {
            float* vC = v[1 - (j & 1)];
            float* vB = v[j & 1];
            float* mA = m3[j % 3];
            float* mB = m3[(j + 2) % 3];
            loadrow6(vB, base + (j + 2) * STR);   // row below center
            hmax3(mB, vB);
            #pragma unroll
            for (int i = 0; i < 4; i++) {
                float p  = vC[i + 1];
                float nb = fmaxf(fmaxf(mA[i], mB[i]), fmaxf(vC[i], vC[i + 2]));
                amin = fminf(amin, p);
                bool  m  = p > nb;                // strict 8-neighbor local max
                float pv = m ? p : -1e30f;
                asum += m ? p : 0.f;
                acnt += m ? 1.f : 0.f;
                t2 = fmaxf(t2, fminf(t1, pv));
                t1 = fmaxf(t1, pv);
            }
        }

        // warp reduction (whole channel lives in this warp)
        #pragma unroll
        for (int off = 16; off > 0; off >>= 1) {
            amin = fminf(amin, __shfl_down_sync(0xffffffffu, amin, off));
            asum += __shfl_down_sync(0xffffffffu, asum, off);
            acnt += __shfl_down_sync(0xffffffffu, acnt, off);
            float b1 = __shfl_down_sync(0xffffffffu, t1, off);
            float b2 = __shfl_down_sync(0xffffffffu, t2, off);
            float lo = fminf(t1, b1);
            t1 = fmaxf(t1, b1);
            t2 = fmaxf(lo, fmaxf(t2, b2));
        }
        if (lane == 0) {
            int bid = blockIdx.y * GB + blockIdx.x;
            int idx = ch * NBLK + bid;
            g_min[idx] = amin; g_sum[idx] = asum; g_cnt[idx] = acnt;
            g_t1[idx]  = t1;   g_t2[idx]  = t2;
        }
    }
}

// 14 blocks x 1024 threads: block c reduces channel c (one float4 per array per thread);
// last block folds the 14 channel losses into the scalar output.
__global__ void reduce_kernel(float* __restrict__ out) {
    __shared__ float s[32][5];
    const int c    = blockIdx.x;
    const int tid  = threadIdx.x;
    const int lane = tid & 31;
    const int warp = tid >> 5;
    const int base = c * NBLK + 4 * tid;

    float4 m4 = *(const float4*)(g_min + base);
    float4 s4 = *(const float4*)(g_sum + base);
    float4 c4 = *(const float4*)(g_cnt + base);
    float4 a4 = *(const float4*)(g_t1  + base);
    float4 b4 = *(const float4*)(g_t2  + base);

    float mn = fminf(fminf(m4.x, m4.y), fminf(m4.z, m4.w));
    float sm = (s4.x + s4.y) + (s4.z + s4.w);
    float ct = (c4.x + c4.y) + (c4.z + c4.w);
    float t1 = a4.x, t2 = b4.x;
    {
        float lo = fminf(t1, a4.y); t1 = fmaxf(t1, a4.y); t2 = fmaxf(lo, fmaxf(t2, b4.y));
        lo = fminf(t1, a4.z); t1 = fmaxf(t1, a4.z); t2 = fmaxf(lo, fmaxf(t2, b4.z));
        lo = fminf(t1, a4.w); t1 = fmaxf(t1, a4.w); t2 = fmaxf(lo, fmaxf(t2, b4.w));
    }

    #pragma unroll
    for (int off = 16; off > 0; off >>= 1) {
        mn = fminf(mn, __shfl_down_sync(0xffffffffu, mn, off));
        sm += __shfl_down_sync(0xffffffffu, sm, off);
        ct += __shfl_down_sync(0xffffffffu, ct, off);
        float b1 = __shfl_down_sync(0xffffffffu, t1, off);
        float b2 = __shfl_down_sync(0xffffffffu, t2, off);
        float lo = fminf(t1, b1);
        t1 = fmaxf(t1, b1);
        t2 = fmaxf(lo, fmaxf(t2, b2));
    }
    if (lane == 0) { s[warp][0]=mn; s[warp][1]=sm; s[warp][2]=ct; s[warp][3]=t1; s[warp][4]=t2; }
    __syncthreads();

    if (tid == 0) {
        mn = s[0][0]; sm = s[0][1]; ct = s[0][2]; t1 = s[0][3]; t2 = s[0][4];
        #pragma unroll
        for (int w = 1; w < 32; w++) {
            mn = fminf(mn, s[w][0]); sm += s[w][1]; ct += s[w][2];
            float b1 = s[w][3], b2 = s[w][4];
            float lo = fminf(t1, b1);
            t1 = fmaxf(t1, b1);
            t2 = fmaxf(lo, fmaxf(t2, b2));
        }
        float total = sm - ct * mn;           // sum of importances over maxima
        float v1 = t1 - mn, v2 = t2 - mn;
        int k = (c < 7) ? 1 : 2;
        float target = 0.f, hinge = 0.f;
        if (ct >= 1.f)           { target += v1; hinge += fmaxf(0.f, 1.f - v1); }
        if (k == 2 && ct >= 2.f) { target += v2; hinge += fmaxf(0.f, 1.f - v2); }
        g_loss[c] = (total - target) + hinge;

        __threadfence();
        unsigned int old = atomicAdd(&g_ctr, 1u);
        if (old == NC - 1) {                  // last block finalizes
            float ssum = 0.f;
            #pragma unroll
            for (int i = 0; i < NC; i++) ssum += g_loss[i];
            out[0] = ssum / (float)NC;
            g_ctr = 0;                        // reset for next graph replay
        }
    }
}

extern "C" void kernel_launch(void* const* d_in, const int* in_sizes, int n_in,
                              void* d_out, int out_size) {
    const float* in = (const float*)d_in[0];   // [1,14,2048,2048] f32 logits
    float* out = (float*)d_out;                // scalar f32

    const size_t smem = (size_t)NC * HD * STR * sizeof(float);   // 68544 B
    cudaFuncSetAttribute(tile_kernel, cudaFuncAttributeMaxDynamicSharedMemorySize, (int)smem);

    dim3 grid(GB, GB);
    tile_kernel<<<grid, 512, smem>>>(in);
    reduce_kernel<<<NC, 1024>>>(out);
}

// round 6
// speedup vs baseline: 1.9179x; 1.2595x over previous
#include <cuda_runtime.h>

#define NC   14
#define H    2048
#define W    2048
#define HW   (H * W)
#define TILE 32
#define HD   34          // tile + halo rows
#define STR  36          // smem row stride (floats); cols 0..32 data, col 34 = left halo
#define GB   64          // blocks per grid dim
#define NBLK (GB * GB)

// Per-block, per-channel partials (fixed slots -> deterministic)
__device__ __align__(16) float g_min[NC * NBLK];
__device__ __align__(16) float g_sum[NC * NBLK];
__device__ __align__(16) float g_cnt[NC * NBLK];
__device__ __align__(16) float g_t1 [NC * NBLK];
__device__ __align__(16) float g_t2 [NC * NBLK];
__device__ float g_loss[NC];
__device__ unsigned int g_ctr;   // zero-init; reset by last reduce block each run

extern __shared__ float sp[];    // [NC][HD][STR] probs

__device__ __forceinline__ float* SP(int ch, int r) {
    return sp + (ch * HD + r) * STR;
}

// ---- packed f32x2 helpers (sm_103a) ----
union F2 { float2 f; unsigned long long u; };

__device__ __forceinline__ float2 f2add(float2 a, float2 b) {
    F2 A, B, R; A.f = a; B.f = b;
    asm("add.rn.f32x2 %0, %1, %2;" : "=l"(R.u) : "l"(A.u), "l"(B.u));
    return R.f;
}
__device__ __forceinline__ float2 f2mul(float2 a, float2 b) {
    F2 A, B, R; A.f = a; B.f = b;
    asm("mul.rn.f32x2 %0, %1, %2;" : "=l"(R.u) : "l"(A.u), "l"(B.u));
    return R.f;
}
// __expf(x) == ex2.approx(x * log2e); pack the multiply, two MUFU for the ex2
__device__ __forceinline__ float2 f2exp(float2 x) {
    const float L2E = 1.4426950408889634f;
    float2 t = f2mul(x, make_float2(L2E, L2E));
    float2 e;
    asm("ex2.approx.f32 %0, %1;" : "=f"(e.x) : "f"(t.x));
    asm("ex2.approx.f32 %0, %1;" : "=f"(e.y) : "f"(t.y));
    return e;
}
__device__ __forceinline__ float2 f2rcp(float2 d) {
    float2 r;
    asm("rcp.approx.f32 %0, %1;" : "=f"(r.x) : "f"(d.x));
    asm("rcp.approx.f32 %0, %1;" : "=f"(r.y) : "f"(d.y));
    return r;
}

// window cols: v[0]=col lcol (left nb), v[1..4]=cols cb..cb+3 (centers), v[5]=col cb+4
__device__ __forceinline__ void loadrow(float v[6], const float* row, int cb, int lcol) {
    v[0] = row[lcol];
    float4 q = *(const float4*)(row + cb);
    v[1] = q.x; v[2] = q.y; v[3] = q.z; v[4] = q.w;
    v[5] = row[cb + 4];
}

__device__ __forceinline__ void hmax3(float m[4], const float v[6]) {
    #pragma unroll
    for (int i = 0; i < 4; i++)
        m[i] = fmaxf(fmaxf(v[i], v[i + 1]), v[i + 2]);
}

__global__ __launch_bounds__(512, 2)   // 64-reg budget: no spills
void tile_kernel(const float* __restrict__ in) {
    const int tid = threadIdx.x;
    const int bx = blockIdx.x, by = blockIdx.y;

    // ---- Phase 1: softmax probs -> smem.
    // Tasks 0..543: vector float2, row r = t>>4, cols 2*(t&15)..+1 (8B aligned in gmem).
    // Tasks 544..611: scalar edges — right col 32 (gx=bx*32+32) and left halo col 34
    // (gx=bx*32-1). Logits ~N(0,1): exp can't overflow, skip max-subtraction.
    for (int t = tid; t < 612; t += 512) {
        if (t < 544) {
            const int r   = t >> 4;
            const int col = 2 * (t & 15);
            const int gy  = by * TILE - 1 + r;
            if ((unsigned)gy < H) {
                const float* g = in + (size_t)gy * W + bx * TILE + col;
                float2 e[NC];
                e[0] = f2exp(*(const float2*)g);
                float2 d = e[0];
                #pragma unroll
                for (int ch = 1; ch < NC; ch++) {
                    e[ch] = f2exp(*(const float2*)(g + ch * HW));
                    d = f2add(d, e[ch]);
                }
                float2 rd = f2rcp(d);
                #pragma unroll
                for (int ch = 0; ch < NC; ch++)
                    *(float2*)(SP(ch, r) + col) = f2mul(e[ch], rd);
            } else {
                const float2 m = make_float2(-1.f, -1.f);
                #pragma unroll
                for (int ch = 0; ch < NC; ch++)
                    *(float2*)(SP(ch, r) + col) = m;   // -inf padding proxy
            }
        } else {
            const int u   = t - 544;
            const int isL = (u >= 34);
            const int r   = isL ? (u - 34) : u;
            const int gy  = by * TILE - 1 + r;
            const int gx  = isL ? (bx * TILE - 1) : (bx * TILE + 32);
            const int col = isL ? 34 : 32;
            if ((unsigned)gy < H && (unsigned)gx < W) {
                const float* g = in + (size_t)gy * W + gx;
                float e[NC];
                float d = 0.f;
                #pragma unroll
                for (int ch = 0; ch < NC; ch++) {
                    e[ch] = __expf(g[ch * HW]);
                    d += e[ch];
                }
                float rd = __fdividef(1.f, d);
                #pragma unroll
                for (int ch = 0; ch < NC; ch++)
                    SP(ch, r)[col] = e[ch] * rd;
            } else {
                #pragma unroll
                for (int ch = 0; ch < NC; ch++)
                    SP(ch, r)[col] = -1.f;
            }
        }
    }
    __syncthreads();

    // ---- Phase 2: warp w owns channel w; lane streams 8 rows x 4 cols.
    const int wid  = tid >> 5;
    const int lane = tid & 31;
    if (wid < NC) {
        const int ch   = wid;
        const int sx   = lane & 7;
        const int cb   = 4 * sx;              // center cols cb..cb+3 (0..31)
        const int lcol = (sx == 0) ? 34 : (cb - 1);
        const int r0   = 8 * (lane >> 3);     // rows r0..r0+9, centers r0+1..r0+8
        const float* base = SP(ch, r0);

        float amin = 1e30f, asum = 0.f, acnt = 0.f, t1 = -1e30f, t2 = -1e30f;

        float v[2][6];
        float m3[3][4];
        {
            float vt[6];
            loadrow(vt, base, cb, lcol);               // row r0 (above)
            hmax3(m3[0], vt);
        }
        loadrow(v[1], base + STR, cb, lcol);           // row r0+1 = first center
        hmax3(m3[1], v[1]);

        #pragma unroll
        for (int j = 0; j < 8; j++) {
            float* vC = v[1 - (j & 1)];
            float* vB = v[j & 1];
            float* mA = m3[j % 3];
            float* mB = m3[(j + 2) % 3];
            loadrow(vB, base + (j + 2) * STR, cb, lcol);   // row below center
            hmax3(mB, vB);
            #pragma unroll
            for (int i = 0; i < 4; i++) {
                float p  = vC[i + 1];
                float nb = fmaxf(fmaxf(mA[i], mB[i]), fmaxf(vC[i], vC[i + 2]));
                amin = fminf(amin, p);
                bool  m  = p > nb;                     // strict 8-neighbor local max
                float pv = m ? p : -1e30f;
                asum += m ? p : 0.f;
                acnt += m ? 1.f : 0.f;
                t2 = fmaxf(t2, fminf(t1, pv));
                t1 = fmaxf(t1, pv);
            }
        }

        // warp reduction (whole channel lives in this warp)
        #pragma unroll
        for (int off = 16; off > 0; off >>= 1) {
            amin = fminf(amin, __shfl_down_sync(0xffffffffu, amin, off));
            asum += __shfl_down_sync(0xffffffffu, asum, off);
            acnt += __shfl_down_sync(0xffffffffu, acnt, off);
            float b1 = __shfl_down_sync(0xffffffffu, t1, off);
            float b2 = __shfl_down_sync(0xffffffffu, t2, off);
            float lo = fminf(t1, b1);
            t1 = fmaxf(t1, b1);
            t2 = fmaxf(lo, fmaxf(t2, b2));
        }
        if (lane == 0) {
            int bid = by * GB + bx;
            int idx = ch * NBLK + bid;
            g_min[idx] = amin; g_sum[idx] = asum; g_cnt[idx] = acnt;
            g_t1[idx]  = t1;   g_t2[idx]  = t2;
        }
    }
}

// 14 blocks x 1024 threads: block c reduces channel c (one float4 per array per thread);
// last block folds the 14 channel losses into the scalar output.
__global__ void reduce_kernel(float* __restrict__ out) {
    __shared__ float s[32][5];
    const int c    = blockIdx.x;
    const int tid  = threadIdx.x;
    const int lane = tid & 31;
    const int warp = tid >> 5;
    const int base = c * NBLK + 4 * tid;

    float4 m4 = *(const float4*)(g_min + base);
    float4 s4 = *(const float4*)(g_sum + base);
    float4 c4 = *(const float4*)(g_cnt + base);
    float4 a4 = *(const float4*)(g_t1  + base);
    float4 b4 = *(const float4*)(g_t2  + base);

    float mn = fminf(fminf(m4.x, m4.y), fminf(m4.z, m4.w));
    float sm = (s4.x + s4.y) + (s4.z + s4.w);
    float ct = (c4.x + c4.y) + (c4.z + c4.w);
    float t1 = a4.x, t2 = b4.x;
    {
        float lo = fminf(t1, a4.y); t1 = fmaxf(t1, a4.y); t2 = fmaxf(lo, fmaxf(t2, b4.y));
        lo = fminf(t1, a4.z); t1 = fmaxf(t1, a4.z); t2 = fmaxf(lo, fmaxf(t2, b4.z));
        lo = fminf(t1, a4.w); t1 = fmaxf(t1, a4.w); t2 = fmaxf(lo, fmaxf(t2, b4.w));
    }

    #pragma unroll
    for (int off = 16; off > 0; off >>= 1) {
        mn = fminf(mn, __shfl_down_sync(0xffffffffu, mn, off));
        sm += __shfl_down_sync(0xffffffffu, sm, off);
        ct += __shfl_down_sync(0xffffffffu, ct, off);
        float b1 = __shfl_down_sync(0xffffffffu, t1, off);
        float b2 = __shfl_down_sync(0xffffffffu, t2, off);
        float lo = fminf(t1, b1);
        t1 = fmaxf(t1, b1);
        t2 = fmaxf(lo, fmaxf(t2, b2));
    }
    if (lane == 0) { s[warp][0]=mn; s[warp][1]=sm; s[warp][2]=ct; s[warp][3]=t1; s[warp][4]=t2; }
    __syncthreads();

    if (tid == 0) {
        mn = s[0][0]; sm = s[0][1]; ct = s[0][2]; t1 = s[0][3]; t2 = s[0][4];
        #pragma unroll
        for (int w = 1; w < 32; w++) {
            mn = fminf(mn, s[w][0]); sm += s[w][1]; ct += s[w][2];
            float b1 = s[w][3], b2 = s[w][4];
            float lo = fminf(t1, b1);
            t1 = fmaxf(t1, b1);
            t2 = fmaxf(lo, fmaxf(t2, b2));
        }
        float total = sm - ct * mn;           // sum of importances over maxima
        float v1 = t1 - mn, v2 = t2 - mn;
        int k = (c < 7) ? 1 : 2;
        float target = 0.f, hinge = 0.f;
        if (ct >= 1.f)           { target += v1; hinge += fmaxf(0.f, 1.f - v1); }
        if (k == 2 && ct >= 2.f) { target += v2; hinge += fmaxf(0.f, 1.f - v2); }
        g_loss[c] = (total - target) + hinge;

        __threadfence();
        unsigned int old = atomicAdd(&g_ctr, 1u);
        if (old == NC - 1) {                  // last block finalizes
            float ssum = 0.f;
            #pragma unroll
            for (int i = 0; i < NC; i++) ssum += g_loss[i];
            out[0] = ssum / (float)NC;
            g_ctr = 0;                        // reset for next graph replay
        }
    }
}

extern "C" void kernel_launch(void* const* d_in, const int* in_sizes, int n_in,
                              void* d_out, int out_size) {
    const float* in = (const float*)d_in[0];   // [1,14,2048,2048] f32 logits
    float* out = (float*)d_out;                // scalar f32

    const size_t smem = (size_t)NC * HD * STR * sizeof(float);   // 68544 B
    cudaFuncSetAttribute(tile_kernel, cudaFuncAttributeMaxDynamicSharedMemorySize, (int)smem);

    dim3 grid(GB, GB);
    tile_kernel<<<grid, 512, smem>>>(in);
    reduce_kernel<<<NC, 1024>>>(out);
}